// round 16
// baseline (speedup 1.0000x reference)
#include <cuda_runtime.h>

#define N_NODES 200000
#define N_EDGES 6400000
#define IN_DIM  1433
#define HID     16
#define OUTD    7
#define OUTP    8
#define SCAN_BLOCKS ((N_NODES + 255) / 256)   // 782
#define KCM      32                            // k-chunk for gemm1
#define MROWS    128                           // rows per gemm1 block (8 warps x 16)
#define NCHM    ((IN_DIM + KCM - 1) / KCM)     // 45
#define GEMM_BLOCKS ((N_NODES + MROWS - 1) / MROWS)   // 1563
#define QUAD_BLOCKS ((N_EDGES / 4 + 255) / 256)       // 6250
#define FAT_BLOCKS (GEMM_BLOCKS + QUAD_BLOCKS)        // 7813

typedef unsigned long long ull;

// -------- scratch (device globals; no runtime allocation allowed) --------
__device__ float g_XW1[N_NODES * HID];          // 12.8 MB  X @ W1
__device__ float g_H  [N_NODES * HID];          // 12.8 MB  L @ (X W1)
__device__ float g_HW2[N_NODES * OUTP];         //  6.4 MB  relu(H+b1) @ W2, padded to 8
__device__ int   g_cnt   [N_NODES];
__device__ int   g_rowptr[N_NODES + 1];
__device__ int   g_pos   [N_NODES];
__device__ int   g_bsum  [SCAN_BLOCKS];
__device__ int   g_boff  [SCAN_BLOCKS];
__device__ ull   g_edge  [N_EDGES];             // 51.2 MB packed (val, col) sorted by row

// tf32 conversion (rna = canonical tf32 rounding; result is a valid fp32 pattern)
__device__ __forceinline__ unsigned f2tf(float x) {
    unsigned r; asm("cvt.rna.tf32.f32 %0, %1;" : "=r"(r) : "f"(x)); return r;
}
// m16n8k8 tf32 MMA, fp32 accumulate
__device__ __forceinline__ void mma_tf32(float& c0, float& c1, float& c2, float& c3,
                                         unsigned a0, unsigned a1, unsigned a2, unsigned a3,
                                         unsigned b0, unsigned b1) {
    asm volatile(
        "mma.sync.aligned.m16n8k8.row.col.f32.tf32.tf32.f32 "
        "{%0,%1,%2,%3}, {%4,%5,%6,%7}, {%8,%9}, {%0,%1,%2,%3};"
        : "+f"(c0), "+f"(c1), "+f"(c2), "+f"(c3)
        : "r"(a0), "r"(a1), "r"(a2), "r"(a3), "r"(b0), "r"(b1));
}

// -------- zero the row counters --------
__global__ void zero_kernel() {
    int i = blockIdx.x * blockDim.x + threadIdx.x;
    if (i < N_NODES) g_cnt[i] = 0;
}

// -------- count edges per row --------
__global__ void __launch_bounds__(256) count_kernel(const int* __restrict__ erow) {
    int q = blockIdx.x * 256 + threadIdx.x;
    if (q >= N_EDGES / 4) return;
    int4 r4 = ((const int4*)erow)[q];
    asm volatile("red.global.add.u32 [%0], 1;" :: "l"(&g_cnt[r4.x]) : "memory");
    asm volatile("red.global.add.u32 [%0], 1;" :: "l"(&g_cnt[r4.y]) : "memory");
    asm volatile("red.global.add.u32 [%0], 1;" :: "l"(&g_cnt[r4.z]) : "memory");
    asm volatile("red.global.add.u32 [%0], 1;" :: "l"(&g_cnt[r4.w]) : "memory");
}

// -------- exclusive scan of g_cnt -> g_rowptr (3-phase) --------
__global__ void __launch_bounds__(256) scan1_kernel() {
    __shared__ int s[256];
    int t = threadIdx.x;
    int i = blockIdx.x * 256 + t;
    int x = (i < N_NODES) ? g_cnt[i] : 0;
    s[t] = x;
    __syncthreads();
#pragma unroll
    for (int d = 1; d < 256; d <<= 1) {
        int y = (t >= d) ? s[t - d] : 0;
        __syncthreads();
        s[t] += y;
        __syncthreads();
    }
    if (i < N_NODES) g_rowptr[i] = s[t] - x;
    if (t == 255) g_bsum[blockIdx.x] = s[t];
}

__global__ void __launch_bounds__(1024) scan2_kernel() {
    __shared__ int s[1024];
    int t = threadIdx.x;
    int x = (t < SCAN_BLOCKS) ? g_bsum[t] : 0;
    s[t] = x;
    __syncthreads();
#pragma unroll
    for (int d = 1; d < 1024; d <<= 1) {
        int y = (t >= d) ? s[t - d] : 0;
        __syncthreads();
        s[t] += y;
        __syncthreads();
    }
    if (t < SCAN_BLOCKS) g_boff[t] = s[t] - x;
}

__global__ void __launch_bounds__(256) scan3_kernel() {
    int i = blockIdx.x * 256 + threadIdx.x;
    if (i < N_NODES) {
        int v = g_rowptr[i] + g_boff[blockIdx.x];
        g_rowptr[i] = v;
        g_pos[i] = v;
    }
    if (i == 0) g_rowptr[N_NODES] = N_EDGES;
}

// -------- FAT kernel: gemm1 (tensor core, DRAM-bound) || scatter (L2/atomic) --------
// These two are independent (scatter needs only the scans; gemm1 feeds spmm1),
// and they stress complementary pipes. 1:4 interleave: bid%5==0 -> gemm tile.
__global__ void __launch_bounds__(256) gemm1_scatter_kernel(const float* __restrict__ X,
                                                            const float* __restrict__ W1,
                                                            const int*   __restrict__ erow,
                                                            const int*   __restrict__ ecol,
                                                            const float* __restrict__ evals) {
    __shared__ float As[MROWS][36];                   // frag banks 4g+ti distinct
    __shared__ unsigned Wh[KCM][24];                  // tf32 hi, banks 24ti+g distinct
    __shared__ unsigned Wl[KCM][24];                  // tf32 lo

    const int bid = blockIdx.x;
    const int g5  = bid / 5;
    if (bid % 5 != 0) {
        // ---------------- scatter block ----------------
        int cb = bid - g5 - 1;                        // 0..QUAD_BLOCKS-1
        int q  = cb * 256 + threadIdx.x;
        if (q < N_EDGES / 4) {
            int4   r4 = ((const int4*)erow)[q];
            int4   c4 = ((const int4*)ecol)[q];
            float4 v4 = ((const float4*)evals)[q];
            int   rr[4] = {r4.x, r4.y, r4.z, r4.w};
            int   cc[4] = {c4.x, c4.y, c4.z, c4.w};
            float vv[4] = {v4.x, v4.y, v4.z, v4.w};
#pragma unroll
            for (int i = 0; i < 4; i++) {
                int p = atomicAdd(&g_pos[rr[i]], 1);
                g_edge[p] = ((ull)__float_as_uint(vv[i]) << 32) | (unsigned)cc[i];
            }
        }
        return;
    }
    // ---------------- gemm1 block ----------------
    const int t    = threadIdx.x;
    const int row0 = g5 * MROWS;
    if (row0 >= N_NODES) return;
    const int lane = t & 31;
    const int wid  = t >> 5;
    const int wrow = wid * 16;
    const int gq   = lane >> 2;
    const int ti   = lane & 3;
    const bool full_rows = (row0 + MROWS <= N_NODES);

    float v[16];                                      // staged A values
    float wv[2];                                      // staged W values
    float c[2][4];
#pragma unroll
    for (int n = 0; n < 2; n++)
#pragma unroll
        for (int j = 0; j < 4; j++) c[n][j] = 0.f;

    auto prefA = [&](int cc) {
        const int kc = cc * KCM;
        const int r  = t >> 5;
        const int k  = t & 31;
        const float* p = X + (long)(row0 + r) * IN_DIM + kc + k;
        if (full_rows && kc + KCM <= IN_DIM) {
#pragma unroll
            for (int s = 0; s < 16; s++) v[s] = p[(long)(8 * s) * IN_DIM];
        } else {
            const bool kok = (kc + k < IN_DIM);
#pragma unroll
            for (int s = 0; s < 16; s++) {
                int rr = row0 + r + 8 * s;
                v[s] = (rr < N_NODES && kok) ? p[(long)(8 * s) * IN_DIM] : 0.f;
            }
        }
    };
    auto prefW = [&](int cc) {
        const int kc = cc * KCM;
#pragma unroll
        for (int s = 0; s < 2; s++) {
            int flat = t + 256 * s;
            int k = flat >> 4, j = flat & 15;
            wv[s] = (kc + k < IN_DIM) ? W1[(kc + k) * HID + j] : 0.f;
        }
    };

    prefA(0); prefW(0);

    for (int cc = 0; cc < NCHM; cc++) {
        // regs -> smem; W split into tf32 hi/lo at staging time (once per chunk)
        {
            const int r = t >> 5, k = t & 31;
#pragma unroll
            for (int s = 0; s < 16; s++) As[r + 8 * s][k] = v[s];
#pragma unroll
            for (int s = 0; s < 2; s++) {
                int flat = t + 256 * s;
                int kk = flat >> 4, jj = flat & 15;
                float w = wv[s];
                unsigned hi = f2tf(w);
                unsigned lo = f2tf(w - __uint_as_float(hi));
                Wh[kk][jj] = hi;
                Wl[kk][jj] = lo;
            }
        }
        __syncthreads();

        if (cc + 1 < NCHM) { prefA(cc + 1); prefW(cc + 1); }

        // compute: 4 k8 steps, 2 n-tiles, 2 MMAs (W_hi, W_lo) per n-tile
#pragma unroll
        for (int k8 = 0; k8 < 4; k8++) {
            const int k0 = k8 * 8;
            unsigned a0 = f2tf(As[wrow + gq    ][k0 + ti    ]);
            unsigned a1 = f2tf(As[wrow + gq + 8][k0 + ti    ]);
            unsigned a2 = f2tf(As[wrow + gq    ][k0 + ti + 4]);
            unsigned a3 = f2tf(As[wrow + gq + 8][k0 + ti + 4]);
#pragma unroll
            for (int n = 0; n < 2; n++) {
                unsigned bh0 = Wh[k0 + ti    ][8 * n + gq];
                unsigned bh1 = Wh[k0 + ti + 4][8 * n + gq];
                unsigned bl0 = Wl[k0 + ti    ][8 * n + gq];
                unsigned bl1 = Wl[k0 + ti + 4][8 * n + gq];
                mma_tf32(c[n][0], c[n][1], c[n][2], c[n][3], a0, a1, a2, a3, bh0, bh1);
                mma_tf32(c[n][0], c[n][1], c[n][2], c[n][3], a0, a1, a2, a3, bl0, bl1);
            }
        }
        __syncthreads();
    }

    const int r0 = row0 + wrow + gq;
    const int r1 = r0 + 8;
#pragma unroll
    for (int n = 0; n < 2; n++) {
        const int col = 8 * n + 2 * ti;
        if (r0 < N_NODES) *(float2*)&g_XW1[r0 * HID + col] = make_float2(c[n][0], c[n][1]);
        if (r1 < N_NODES) *(float2*)&g_XW1[r1 * HID + col] = make_float2(c[n][2], c[n][3]);
    }
}

// -------- SPMM1: warp per row, 4 lanes per edge (float4 gathers), 8 edges/iter --------
__global__ void __launch_bounds__(256) spmm1_kernel() {
    int warp = (blockIdx.x * 256 + threadIdx.x) >> 5;
    if (warp >= N_NODES) return;
    int lane = threadIdx.x & 31;
    int e    = lane >> 2;                 // edge sub-slot 0..7
    int dg   = lane & 3;                  // dim group (4 floats)

    int start = g_rowptr[warp];
    int end   = g_rowptr[warp + 1];

    float4 acc = make_float4(0.f, 0.f, 0.f, 0.f);
    int i = start + e;
    for (; i + 8 < end; i += 16) {        // 2 edges per lane-slot in flight
        ull e0 = g_edge[i];
        ull e1 = g_edge[i + 8];
        int   c0 = (int)(unsigned)e0;  float v0 = __uint_as_float((unsigned)(e0 >> 32));
        int   c1 = (int)(unsigned)e1;  float v1 = __uint_as_float((unsigned)(e1 >> 32));
        float4 x0 = *(const float4*)&g_XW1[c0 * HID + 4 * dg];
        float4 x1 = *(const float4*)&g_XW1[c1 * HID + 4 * dg];
        acc.x = fmaf(v0, x0.x, acc.x); acc.y = fmaf(v0, x0.y, acc.y);
        acc.z = fmaf(v0, x0.z, acc.z); acc.w = fmaf(v0, x0.w, acc.w);
        acc.x = fmaf(v1, x1.x, acc.x); acc.y = fmaf(v1, x1.y, acc.y);
        acc.z = fmaf(v1, x1.z, acc.z); acc.w = fmaf(v1, x1.w, acc.w);
    }
    if (i < end) {
        ull e0 = g_edge[i];
        int   c0 = (int)(unsigned)e0;  float v0 = __uint_as_float((unsigned)(e0 >> 32));
        float4 x0 = *(const float4*)&g_XW1[c0 * HID + 4 * dg];
        acc.x = fmaf(v0, x0.x, acc.x); acc.y = fmaf(v0, x0.y, acc.y);
        acc.z = fmaf(v0, x0.z, acc.z); acc.w = fmaf(v0, x0.w, acc.w);
    }
    // reduce across edge sub-slots (lane bits 2,3,4)
#pragma unroll
    for (int m = 4; m <= 16; m <<= 1) {
        acc.x += __shfl_xor_sync(0xffffffff, acc.x, m);
        acc.y += __shfl_xor_sync(0xffffffff, acc.y, m);
        acc.z += __shfl_xor_sync(0xffffffff, acc.z, m);
        acc.w += __shfl_xor_sync(0xffffffff, acc.w, m);
    }
    if (lane < 4) *(float4*)&g_H[warp * HID + 4 * lane] = acc;
}

// -------- GEMM2  g_HW2 = relu(g_H + b1) @ W2, padded to 8 cols --------
__global__ void __launch_bounds__(256) gemm2_kernel(const float* __restrict__ b1,
                                                    const float* __restrict__ W2) {
    __shared__ float sW2[HID * OUTD];
    __shared__ float sb1[HID];
    int t = threadIdx.x;
    if (t < HID * OUTD) sW2[t] = W2[t];
    if (t < HID)        sb1[t] = b1[t];
    __syncthreads();

    int i = blockIdx.x * 256 + t;
    if (i >= N_NODES) return;

    const float4* hp = (const float4*)&g_H[i * HID];
    float h[16];
    *(float4*)&h[0]  = hp[0]; *(float4*)&h[4]  = hp[1];
    *(float4*)&h[8]  = hp[2]; *(float4*)&h[12] = hp[3];
#pragma unroll
    for (int j = 0; j < 16; j++) h[j] = fmaxf(h[j] + sb1[j], 0.f);

    float o[OUTP];
#pragma unroll
    for (int c = 0; c < OUTD; c++) {
        float s = 0.f;
#pragma unroll
        for (int j = 0; j < HID; j++) s = fmaf(h[j], sW2[j * OUTD + c], s);
        o[c] = s;
    }
    o[7] = 0.f;

    float4* d = (float4*)&g_HW2[i * OUTP];
    d[0] = *(float4*)&o[0];
    d[1] = *(float4*)&o[4];
}

// -------- SPMM2 + bias fused: warp per row, 2 lanes per edge, 16 edges/iter --------
__global__ void __launch_bounds__(256) spmm2_kernel(const float* __restrict__ b2,
                                                    float* __restrict__ out) {
    int warp = (blockIdx.x * 256 + threadIdx.x) >> 5;
    if (warp >= N_NODES) return;
    int lane = threadIdx.x & 31;
    int e    = lane >> 1;                 // edge sub-slot 0..15
    int dg   = lane & 1;                  // dim group (4 floats)

    int start = g_rowptr[warp];
    int end   = g_rowptr[warp + 1];

    float4 acc = make_float4(0.f, 0.f, 0.f, 0.f);
    int i = start + e;
    for (; i + 16 < end; i += 32) {
        ull e0 = g_edge[i];
        ull e1 = g_edge[i + 16];
        int   c0 = (int)(unsigned)e0;  float v0 = __uint_as_float((unsigned)(e0 >> 32));
        int   c1 = (int)(unsigned)e1;  float v1 = __uint_as_float((unsigned)(e1 >> 32));
        float4 x0 = *(const float4*)&g_HW2[c0 * OUTP + 4 * dg];
        float4 x1 = *(const float4*)&g_HW2[c1 * OUTP + 4 * dg];
        acc.x = fmaf(v0, x0.x, acc.x); acc.y = fmaf(v0, x0.y, acc.y);
        acc.z = fmaf(v0, x0.z, acc.z); acc.w = fmaf(v0, x0.w, acc.w);
        acc.x = fmaf(v1, x1.x, acc.x); acc.y = fmaf(v1, x1.y, acc.y);
        acc.z = fmaf(v1, x1.z, acc.z); acc.w = fmaf(v1, x1.w, acc.w);
    }
    if (i < end) {
        ull e0 = g_edge[i];
        int   c0 = (int)(unsigned)e0;  float v0 = __uint_as_float((unsigned)(e0 >> 32));
        float4 x0 = *(const float4*)&g_HW2[c0 * OUTP + 4 * dg];
        acc.x = fmaf(v0, x0.x, acc.x); acc.y = fmaf(v0, x0.y, acc.y);
        acc.z = fmaf(v0, x0.z, acc.z); acc.w = fmaf(v0, x0.w, acc.w);
    }
    // reduce across edge sub-slots (lane bits 1..4)
#pragma unroll
    for (int m = 2; m <= 16; m <<= 1) {
        acc.x += __shfl_xor_sync(0xffffffff, acc.x, m);
        acc.y += __shfl_xor_sync(0xffffffff, acc.y, m);
        acc.z += __shfl_xor_sync(0xffffffff, acc.z, m);
        acc.w += __shfl_xor_sync(0xffffffff, acc.w, m);
    }
    if (lane < 2) {
        int base = warp * OUTD + 4 * lane;
        float vals[4] = {acc.x, acc.y, acc.z, acc.w};
#pragma unroll
        for (int k = 0; k < 4; k++) {
            int col = 4 * lane + k;
            if (col < OUTD) out[base + k] = vals[k] + b2[col];
        }
    }
}

extern "C" void kernel_launch(void* const* d_in, const int* in_sizes, int n_in,
                              void* d_out, int out_size) {
    const float* feature = (const float*)d_in[0];
    const int*   erow    = (const int*)  d_in[1];
    const int*   ecol    = (const int*)  d_in[2];
    const float* evals   = (const float*)d_in[3];
    const float* W1      = (const float*)d_in[4];
    const float* b1      = (const float*)d_in[5];
    const float* W2      = (const float*)d_in[6];
    const float* b2      = (const float*)d_in[7];
    float* out = (float*)d_out;

    int node_blocks = (N_NODES + 255) / 256;               // 782
    int warp_blocks = (N_NODES * 32 + 255) / 256;          // 25000

    zero_kernel<<<node_blocks, 256>>>();                   // 0
    count_kernel<<<QUAD_BLOCKS, 256>>>(erow);              // 1
    scan1_kernel<<<SCAN_BLOCKS, 256>>>();                  // 2
    scan2_kernel<<<1, 1024>>>();                           // 3
    scan3_kernel<<<SCAN_BLOCKS, 256>>>();                  // 4
    gemm1_scatter_kernel<<<FAT_BLOCKS, 256>>>(feature, W1, erow, ecol, evals);  // 5
    spmm1_kernel<<<warp_blocks, 256>>>();                  // 6
    gemm2_kernel<<<node_blocks, 256>>>(b1, W2);            // 7
    spmm2_kernel<<<warp_blocks, 256>>>(b2, out);           // 8
}